// round 13
// baseline (speedup 1.0000x reference)
#include <cuda_runtime.h>
#include <cuda_fp16.h>
#include <math.h>
#include <stdint.h>

#define LL 512
#define DS 256
#define HH 32
#define DP 128
#define KRBF 36

// ---------------- scratch globals ----------------
__device__ float    g_left[LL * HH];
__device__ float    g_right[LL * HH];      // [m][32] fp32
__device__ float    g_cas[LL * 4];
__device__ uint32_t g_tp[LL * DP * 16];    // t^T fp16: [l][p][16 words = 32 k]
__device__ uint32_t g_wr[DP * 24];         // w_rbf^T fp16: [p][24 words = 48 k]

// ---------------- helpers ----------------
__device__ __forceinline__ uint32_t smem_u32(const void* p) {
    uint32_t a;
    asm("{ .reg .u64 t; cvta.to.shared.u64 t, %1; cvt.u32.u64 %0, t; }" : "=r"(a) : "l"(p));
    return a;
}
__device__ __forceinline__ uint32_t pk2(float a, float b) {
    __half2 h = __floats2half2_rn(a, b);
    return *(uint32_t*)&h;
}
__device__ __forceinline__ void mma16816(float d[4], const uint32_t a[4], const uint32_t b[2]) {
    asm volatile("mma.sync.aligned.m16n8k16.row.col.f32.f16.f16.f32 "
        "{%0,%1,%2,%3}, {%4,%5,%6,%7}, {%8,%9}, {%0,%1,%2,%3};"
        : "+f"(d[0]), "+f"(d[1]), "+f"(d[2]), "+f"(d[3])
        : "r"(a[0]), "r"(a[1]), "r"(a[2]), "r"(a[3]), "r"(b[0]), "r"(b[1]));
}
__device__ __forceinline__ void ldmx4(uint32_t r[4], uint32_t addr) {
    asm volatile("ldmatrix.sync.aligned.m8n8.x4.shared.b16 {%0,%1,%2,%3}, [%4];"
        : "=r"(r[0]), "=r"(r[1]), "=r"(r[2]), "=r"(r[3]) : "r"(addr));
}
__device__ __forceinline__ float sigmoid_t(float x) {
    float t;
    asm("tanh.approx.f32 %0, %1;" : "=f"(t) : "f"(0.5f * x));
    return fmaf(0.5f, t, 0.5f);
}

// ---------------------------------------------------------------------------
// k_prep (proven): LayerNorm + left/right projections + cas; block 0 packs w_rbf^T
// ---------------------------------------------------------------------------
__global__ __launch_bounds__(256) void k_prep(
    const float* __restrict__ xyz, const float* __restrict__ state,
    const float* __restrict__ ln_w, const float* __restrict__ ln_b,
    const float* __restrict__ w_left, const float* __restrict__ b_left,
    const float* __restrict__ w_right, const float* __restrict__ b_right,
    const float* __restrict__ w_rbf)
{
    int l = blockIdx.x, tid = threadIdx.x;
    __shared__ float st_s[DS];
    __shared__ float red[18];
    __shared__ float part[64][4];

    float x = state[l * DS + tid];
    float s = x, q = x * x;
    #pragma unroll
    for (int o = 16; o; o >>= 1) {
        s += __shfl_xor_sync(0xFFFFFFFFu, s, o);
        q += __shfl_xor_sync(0xFFFFFFFFu, q, o);
    }
    int wid = tid >> 5, lane = tid & 31;
    if (lane == 0) { red[wid] = s; red[8 + wid] = q; }
    __syncthreads();
    if (tid == 0) {
        float S = 0.f, Q = 0.f;
        #pragma unroll
        for (int i = 0; i < 8; i++) { S += red[i]; Q += red[8 + i]; }
        float mu = S * (1.0f / DS);
        float var = Q * (1.0f / DS) - mu * mu;
        red[16] = mu; red[17] = rsqrtf(var + 1e-5f);
    }
    __syncthreads();
    st_s[tid] = (x - red[16]) * red[17] * ln_w[tid] + ln_b[tid];
    __syncthreads();

    {
        int j = tid & 31, half = (tid >> 5) & 1, seg = tid >> 6;
        const float* w = half ? w_right : w_left;
        float acc = 0.f;
        int i0 = seg * 64;
        #pragma unroll 8
        for (int i = 0; i < 64; i++) acc += st_s[i0 + i] * w[(i0 + i) * HH + j];
        part[half * 32 + j][seg] = acc;
    }
    __syncthreads();
    if (tid < 64) {
        int j = tid & 31, half = tid >> 5;
        float a = part[tid][0] + part[tid][1] + part[tid][2] + part[tid][3]
                + (half ? b_right[j] : b_left[j]);
        if (half) g_right[l * HH + j] = a;
        else      g_left[l * HH + j] = a;
    }
    if (tid < 3) g_cas[l * 4 + tid] = xyz[l * 9 + 3 + tid];

    if (blockIdx.x == 0 && tid < DP) {
        #pragma unroll
        for (int c = 0; c < 24; c++) {
            int k0 = 2 * c, k1 = 2 * c + 1;
            float v0 = (k0 < KRBF) ? w_rbf[k0 * DP + tid] : 0.f;
            float v1 = (k1 < KRBF) ? w_rbf[k1 * DP + tid] : 0.f;
            g_wr[tid * 24 + c] = pk2(v0, v1);
        }
    }
}

// ---------------------------------------------------------------------------
// k_t: t[l,k,p] = sum_i left[l,i]*Wg[i,k,p]; emit t^T fp16 [l][p][k], stride 16
// grid = (64 lb, 8 jb): 8 l x 4 j x 128 p per block, 128 threads
// ---------------------------------------------------------------------------
__global__ __launch_bounds__(128) void k_t(const float* __restrict__ w_gate)
{
    __shared__ float ls[8 * HH];
    int lb = blockIdx.x * 8, j0 = blockIdx.y * 4, p = threadIdx.x;
    for (int i = p; i < 8 * HH; i += 128) ls[i] = g_left[lb * HH + i];
    __syncthreads();

    float acc[8][4];
    #pragma unroll
    for (int lt = 0; lt < 8; lt++)
        #pragma unroll
        for (int qj = 0; qj < 4; qj++) acc[lt][qj] = 0.f;

    #pragma unroll 4
    for (int i = 0; i < HH; i++) {
        float wv[4];
        #pragma unroll
        for (int qj = 0; qj < 4; qj++)
            wv[qj] = w_gate[(i * HH + j0 + qj) * DP + p];
        #pragma unroll
        for (int lt = 0; lt < 8; lt++) {
            float lv = ls[lt * HH + i];
            #pragma unroll
            for (int qj = 0; qj < 4; qj++) acc[lt][qj] += lv * wv[qj];
        }
    }
    int c0 = j0 >> 1;
    #pragma unroll
    for (int lt = 0; lt < 8; lt++) {
        uint32_t h0 = pk2(acc[lt][0], acc[lt][1]);
        uint32_t h1 = pk2(acc[lt][2], acc[lt][3]);
        uint32_t base = (uint32_t)((lb + lt) * DP + p) * 16u + c0;
        *(uint2*)(g_tp + base) = make_uint2(h0, h1);
    }
}

// ---------------------------------------------------------------------------
// k_main: fp16 single-product, m-tile 128 (grid 512 x 4), 8 warps, 3 blocks/SM.
// Warp covers two 32m x 32p subtiles sequentially (register reuse).
// A1 = right [128][80B], A2 = rbf [128][112B], B1 = t^T [128][80B],
// B2 = wrbf^T [128][112B]. Early sigmoid (tanh.approx) -> half2 gate.
// ---------------------------------------------------------------------------
#define A1H 0
#define A2H 10240
#define B1H 24576
#define B2H 34816
#define SMTOT 49152

__global__ __launch_bounds__(256, 3) void k_main(
    const float* __restrict__ b_rbf, const float* __restrict__ b_gate,
    float* __restrict__ out)
{
    extern __shared__ char smem[];
    __shared__ float dist_s[128];
    uint32_t sb = smem_u32(smem);
    int tid = threadIdx.x, lane = tid & 31, wid = tid >> 5;
    int l = blockIdx.x, mb = blockIdx.y * 128;

    if (tid < 128) {
        int m = mb + tid;
        float dx = g_cas[m * 4]     - g_cas[l * 4];
        float dy = g_cas[m * 4 + 1] - g_cas[l * 4 + 1];
        float dz = g_cas[m * 4 + 2] - g_cas[l * 4 + 2];
        dist_s[tid] = sqrtf(fmaxf(dx * dx + dy * dy + dz * dz, 1e-12f));
    }

    // A1 fill: right -> fp16 [128][80B] (512 chunks)
    #pragma unroll
    for (int it = 0; it < 2; it++) {
        int idx = it * 256 + tid;
        int row = idx >> 2, ch = idx & 3;
        const float4* src = (const float4*)(g_right + (mb + row) * HH + ch * 8);
        float4 x = src[0], y = src[1];
        uint4 h = make_uint4(pk2(x.x, x.y), pk2(x.z, x.w), pk2(y.x, y.y), pk2(y.z, y.w));
        *(uint4*)(smem + A1H + row * 80 + ch * 16) = h;
    }
    // B1 fill: t^T [128][80B] (512 chunks)
    #pragma unroll
    for (int it = 0; it < 2; it++) {
        int idx = it * 256 + tid;
        int row = idx >> 2, ch = idx & 3;
        uint32_t gb = (uint32_t)(l * DP + row) * 16u + ch * 4;
        *(uint4*)(smem + B1H + row * 80 + ch * 16) = *(const uint4*)(g_tp + gb);
    }
    // B2 fill: w_rbf^T [128][112B] (768 chunks)
    #pragma unroll
    for (int it = 0; it < 3; it++) {
        int idx = it * 256 + tid;
        int row = idx / 6, ch = idx - row * 6;
        *(uint4*)(smem + B2H + row * 112 + ch * 16) = *(const uint4*)(g_wr + row * 24 + ch * 4);
    }
    __syncthreads();

    // A2 fill: rbf features fp16 [128][112B] (512 tasks of 12 k)
    #pragma unroll
    for (int it = 0; it < 2; it++) {
        int idx = it * 256 + tid;
        int m = idx >> 2, kg = idx & 3;
        float dist = dist_s[m];
        const float DMU = 20.0f / 35.0f, INV_SIG = 36.0f / 20.0f;
        #pragma unroll
        for (int kk = 0; kk < 6; kk++) {
            int k = kg * 12 + 2 * kk;
            float e0 = 0.f, e1 = 0.f;
            if (k < KRBF) {
                float u = (dist - (2.0f + (float)k * DMU)) * INV_SIG;
                e0 = __expf(-u * u);
            }
            if (k + 1 < KRBF) {
                float u = (dist - (2.0f + (float)(k + 1) * DMU)) * INV_SIG;
                e1 = __expf(-u * u);
            }
            *(uint32_t*)(smem + A2H + m * 112 + k * 2) = pk2(e0, e1);
        }
    }
    __syncthreads();

    // ---- ldmatrix address components ----
    uint32_t rr = lane & 7, q = lane >> 3;
    uint32_t a_r = (q & 1) << 3, a_k = (q >> 1) << 3;
    uint32_t b_r = (q >> 1) << 3, b_k = (q & 1) << 3;
    int M0b = (wid & 1) * 32, P0 = (wid >> 1) * 32;
    int r0 = lane >> 2, c2 = (lane & 3) * 2;

    for (int msub = 0; msub < 2; msub++) {
        int M0 = M0b + msub * 64;

        // ---- pass 1: logits (K=32, 2 ks) ----
        uint32_t Ah[2][2][4];
        #pragma unroll
        for (int mt = 0; mt < 2; mt++)
            #pragma unroll
            for (int ks = 0; ks < 2; ks++)
                ldmx4(Ah[mt][ks], sb + A1H + (M0 + mt * 16 + rr + a_r) * 80 + (ks * 16 + a_k) * 2);

        float accL[2][4][4];
        #pragma unroll
        for (int mt = 0; mt < 2; mt++)
            #pragma unroll
            for (int nt = 0; nt < 4; nt++)
                #pragma unroll
                for (int j = 0; j < 4; j++) accL[mt][nt][j] = 0.f;

        #pragma unroll
        for (int npp = 0; npp < 2; npp++) {
            int n0 = P0 + npp * 16;
            uint32_t bbase = sb + B1H + (n0 + rr + b_r) * 80 + b_k * 2;
            #pragma unroll
            for (int ks = 0; ks < 2; ks++) {
                uint32_t bh[4];
                ldmx4(bh, bbase + ks * 32);
                #pragma unroll
                for (int mt = 0; mt < 2; mt++) {
                    mma16816(accL[mt][2 * npp],     Ah[mt][ks], bh);
                    mma16816(accL[mt][2 * npp + 1], Ah[mt][ks], bh + 2);
                }
            }
        }

        // ---- early sigmoid -> half2 gate ----
        uint32_t gate[2][4][2];
        #pragma unroll
        for (int nt = 0; nt < 4; nt++) {
            int pg = P0 + nt * 8 + c2;
            float2 bg = *(const float2*)(b_gate + pg);
            #pragma unroll
            for (int mt = 0; mt < 2; mt++) {
                gate[mt][nt][0] = pk2(sigmoid_t(accL[mt][nt][0] + bg.x),
                                      sigmoid_t(accL[mt][nt][1] + bg.y));
                gate[mt][nt][1] = pk2(sigmoid_t(accL[mt][nt][2] + bg.x),
                                      sigmoid_t(accL[mt][nt][3] + bg.y));
            }
        }

        // ---- pass 2: feat (K=48, 3 ks) + fused epilogue ----
        uint32_t Fh[2][3][4];
        #pragma unroll
        for (int mt = 0; mt < 2; mt++)
            #pragma unroll
            for (int ks = 0; ks < 3; ks++)
                ldmx4(Fh[mt][ks], sb + A2H + (M0 + mt * 16 + rr + a_r) * 112 + (ks * 16 + a_k) * 2);

        #pragma unroll
        for (int npp = 0; npp < 2; npp++) {
            int n0 = P0 + npp * 16;
            uint32_t bbase = sb + B2H + (n0 + rr + b_r) * 112 + b_k * 2;
            float accF[2][2][4];
            #pragma unroll
            for (int mt = 0; mt < 2; mt++)
                #pragma unroll
                for (int nt = 0; nt < 2; nt++)
                    #pragma unroll
                    for (int j = 0; j < 4; j++) accF[mt][nt][j] = 0.f;
            #pragma unroll
            for (int ks = 0; ks < 3; ks++) {
                uint32_t bh[4];
                ldmx4(bh, bbase + ks * 32);
                #pragma unroll
                for (int mt = 0; mt < 2; mt++) {
                    mma16816(accF[mt][0], Fh[mt][ks], bh);
                    mma16816(accF[mt][1], Fh[mt][ks], bh + 2);
                }
            }
            #pragma unroll
            for (int mt = 0; mt < 2; mt++) {
                #pragma unroll
                for (int ntl = 0; ntl < 2; ntl++) {
                    int nt = 2 * npp + ntl;
                    int pg = P0 + nt * 8 + c2;
                    float2 br = *(const float2*)(b_rbf + pg);
                    const float* Fc = accF[mt][ntl];
                    float2 g0 = __half22float2(*(const __half2*)&gate[mt][nt][0]);
                    float2 g1 = __half22float2(*(const __half2*)&gate[mt][nt][1]);
                    int m0 = mb + M0 + mt * 16 + r0;
                    float* o0 = out + ((size_t)l * LL + m0) * DP + pg;
                    float2 v0, v1;
                    v0.x = (Fc[0] + br.x) * g0.x;
                    v0.y = (Fc[1] + br.y) * g0.y;
                    v1.x = (Fc[2] + br.x) * g1.x;
                    v1.y = (Fc[3] + br.y) * g1.y;
                    *(float2*)o0 = v0;
                    *(float2*)(o0 + 8 * DP) = v1;
                }
            }
        }
    }
}

// ---------------------------------------------------------------------------
extern "C" void kernel_launch(void* const* d_in, const int* in_sizes, int n_in,
                              void* d_out, int out_size)
{
    const float* xyz     = (const float*)d_in[0];
    const float* state   = (const float*)d_in[1];
    const float* ln_w    = (const float*)d_in[2];
    const float* ln_b    = (const float*)d_in[3];
    const float* w_rbf   = (const float*)d_in[4];
    const float* b_rbf   = (const float*)d_in[5];
    const float* w_left  = (const float*)d_in[6];
    const float* b_left  = (const float*)d_in[7];
    const float* w_right = (const float*)d_in[8];
    const float* b_right = (const float*)d_in[9];
    const float* w_gate  = (const float*)d_in[10];
    const float* b_gate  = (const float*)d_in[11];
    float* out = (float*)d_out;

    k_prep<<<LL, 256>>>(xyz, state, ln_w, ln_b, w_left, b_left, w_right, b_right, w_rbf);
    k_t<<<dim3(64, 8), 128>>>(w_gate);

    cudaFuncSetAttribute(k_main, cudaFuncAttributeMaxDynamicSharedMemorySize, SMTOT);
    k_main<<<dim3(LL, 4), 256, SMTOT>>>(b_rbf, b_gate, out);
}

// round 14
// speedup vs baseline: 1.5218x; 1.5218x over previous
#include <cuda_runtime.h>
#include <cuda_fp16.h>
#include <math.h>
#include <stdint.h>

#define LL 512
#define DS 256
#define HH 32
#define DP 128
#define KRBF 36

// ---------------- scratch globals ----------------
__device__ float    g_left[LL * HH];
__device__ float    g_right[LL * HH];      // [m][32] fp32
__device__ float    g_cas[LL * 4];
__device__ uint32_t g_tp[LL * DP * 16];    // t^T fp16: [l][p][16 words = 32 k]
__device__ uint32_t g_wr[DP * 24];         // w_rbf^T fp16: [p][24 words = 48 k]

// ---------------- helpers ----------------
__device__ __forceinline__ uint32_t smem_u32(const void* p) {
    uint32_t a;
    asm("{ .reg .u64 t; cvta.to.shared.u64 t, %1; cvt.u32.u64 %0, t; }" : "=r"(a) : "l"(p));
    return a;
}
__device__ __forceinline__ uint32_t pk2(float a, float b) {
    __half2 h = __floats2half2_rn(a, b);
    return *(uint32_t*)&h;
}
__device__ __forceinline__ void mma16816(float d[4], const uint32_t a[4], const uint32_t b[2]) {
    asm volatile("mma.sync.aligned.m16n8k16.row.col.f32.f16.f16.f32 "
        "{%0,%1,%2,%3}, {%4,%5,%6,%7}, {%8,%9}, {%0,%1,%2,%3};"
        : "+f"(d[0]), "+f"(d[1]), "+f"(d[2]), "+f"(d[3])
        : "r"(a[0]), "r"(a[1]), "r"(a[2]), "r"(a[3]), "r"(b[0]), "r"(b[1]));
}
__device__ __forceinline__ void ldmx4(uint32_t r[4], uint32_t addr) {
    asm volatile("ldmatrix.sync.aligned.m8n8.x4.shared.b16 {%0,%1,%2,%3}, [%4];"
        : "=r"(r[0]), "=r"(r[1]), "=r"(r[2]), "=r"(r[3]) : "r"(addr));
}
__device__ __forceinline__ float sigmoid_t(float x) {
    float t;
    asm("tanh.approx.f32 %0, %1;" : "=f"(t) : "f"(0.5f * x));
    return fmaf(0.5f, t, 0.5f);
}

// ---------------------------------------------------------------------------
// k_prep (proven): LayerNorm + left/right projections + cas; block 0 packs w_rbf^T
// ---------------------------------------------------------------------------
__global__ __launch_bounds__(256) void k_prep(
    const float* __restrict__ xyz, const float* __restrict__ state,
    const float* __restrict__ ln_w, const float* __restrict__ ln_b,
    const float* __restrict__ w_left, const float* __restrict__ b_left,
    const float* __restrict__ w_right, const float* __restrict__ b_right,
    const float* __restrict__ w_rbf)
{
    int l = blockIdx.x, tid = threadIdx.x;
    __shared__ float st_s[DS];
    __shared__ float red[18];
    __shared__ float part[64][4];

    float x = state[l * DS + tid];
    float s = x, q = x * x;
    #pragma unroll
    for (int o = 16; o; o >>= 1) {
        s += __shfl_xor_sync(0xFFFFFFFFu, s, o);
        q += __shfl_xor_sync(0xFFFFFFFFu, q, o);
    }
    int wid = tid >> 5, lane = tid & 31;
    if (lane == 0) { red[wid] = s; red[8 + wid] = q; }
    __syncthreads();
    if (tid == 0) {
        float S = 0.f, Q = 0.f;
        #pragma unroll
        for (int i = 0; i < 8; i++) { S += red[i]; Q += red[8 + i]; }
        float mu = S * (1.0f / DS);
        float var = Q * (1.0f / DS) - mu * mu;
        red[16] = mu; red[17] = rsqrtf(var + 1e-5f);
    }
    __syncthreads();
    st_s[tid] = (x - red[16]) * red[17] * ln_w[tid] + ln_b[tid];
    __syncthreads();

    {
        int j = tid & 31, half = (tid >> 5) & 1, seg = tid >> 6;
        const float* w = half ? w_right : w_left;
        float acc = 0.f;
        int i0 = seg * 64;
        #pragma unroll 8
        for (int i = 0; i < 64; i++) acc += st_s[i0 + i] * w[(i0 + i) * HH + j];
        part[half * 32 + j][seg] = acc;
    }
    __syncthreads();
    if (tid < 64) {
        int j = tid & 31, half = tid >> 5;
        float a = part[tid][0] + part[tid][1] + part[tid][2] + part[tid][3]
                + (half ? b_right[j] : b_left[j]);
        if (half) g_right[l * HH + j] = a;
        else      g_left[l * HH + j] = a;
    }
    if (tid < 3) g_cas[l * 4 + tid] = xyz[l * 9 + 3 + tid];

    if (blockIdx.x == 0 && tid < DP) {
        #pragma unroll
        for (int c = 0; c < 24; c++) {
            int k0 = 2 * c, k1 = 2 * c + 1;
            float v0 = (k0 < KRBF) ? w_rbf[k0 * DP + tid] : 0.f;
            float v1 = (k1 < KRBF) ? w_rbf[k1 * DP + tid] : 0.f;
            g_wr[tid * 24 + c] = pk2(v0, v1);
        }
    }
}

// ---------------------------------------------------------------------------
// k_t: t[l,k,p] = sum_i left[l,i]*Wg[i,k,p]; emit t^T fp16 [l][p][k], stride 16
// grid = (64 lb, 8 jb): 8 l x 4 j x 128 p per block, 128 threads
// ---------------------------------------------------------------------------
__global__ __launch_bounds__(128) void k_t(const float* __restrict__ w_gate)
{
    __shared__ float ls[8 * HH];
    int lb = blockIdx.x * 8, j0 = blockIdx.y * 4, p = threadIdx.x;
    for (int i = p; i < 8 * HH; i += 128) ls[i] = g_left[lb * HH + i];
    __syncthreads();

    float acc[8][4];
    #pragma unroll
    for (int lt = 0; lt < 8; lt++)
        #pragma unroll
        for (int qj = 0; qj < 4; qj++) acc[lt][qj] = 0.f;

    #pragma unroll 4
    for (int i = 0; i < HH; i++) {
        float wv[4];
        #pragma unroll
        for (int qj = 0; qj < 4; qj++)
            wv[qj] = w_gate[(i * HH + j0 + qj) * DP + p];
        #pragma unroll
        for (int lt = 0; lt < 8; lt++) {
            float lv = ls[lt * HH + i];
            #pragma unroll
            for (int qj = 0; qj < 4; qj++) acc[lt][qj] += lv * wv[qj];
        }
    }
    int c0 = j0 >> 1;   // word index 0..14, 2 words per block
    #pragma unroll
    for (int lt = 0; lt < 8; lt++) {
        uint32_t h0 = pk2(acc[lt][0], acc[lt][1]);
        uint32_t h1 = pk2(acc[lt][2], acc[lt][3]);
        uint32_t base = (uint32_t)((lb + lt) * DP + p) * 16u + c0;
        *(uint2*)(g_tp + base) = make_uint2(h0, h1);
    }
}

// ---------------------------------------------------------------------------
// k_main: mma.sync fp16 single-product, natural regs (no min-blocks cap).
// Block = (l, 64 m) x 128 p, 8 warps; warp tile 32m x 32p.
// Early sigmoid after pass 1 (tanh.approx), gate kept as half2.
// Direct float2 stores. smem 36864 B.
// ---------------------------------------------------------------------------
#define A1H 0
#define A2H 5120
#define B1H 12288
#define B2H 22528
#define SMTOT 36864

__global__ __launch_bounds__(256) void k_main(
    const float* __restrict__ b_rbf, const float* __restrict__ b_gate,
    float* __restrict__ out)
{
    extern __shared__ char smem[];
    __shared__ float dist_s[64];
    uint32_t sb = smem_u32(smem);
    int tid = threadIdx.x, lane = tid & 31, wid = tid >> 5;
    int l = blockIdx.x, mb = blockIdx.y * 64;

    if (tid < 64) {
        int m = mb + tid;
        float dx = g_cas[m * 4]     - g_cas[l * 4];
        float dy = g_cas[m * 4 + 1] - g_cas[l * 4 + 1];
        float dz = g_cas[m * 4 + 2] - g_cas[l * 4 + 2];
        dist_s[tid] = sqrtf(fmaxf(dx * dx + dy * dy + dz * dz, 1e-12f));
    }

    // A1 fill: right -> fp16 [64][80B]
    {
        int row = tid >> 2, ch = tid & 3;
        const float4* src = (const float4*)(g_right + (mb + row) * HH + ch * 8);
        float4 x = src[0], y = src[1];
        uint4 h = make_uint4(pk2(x.x, x.y), pk2(x.z, x.w), pk2(y.x, y.y), pk2(y.z, y.w));
        *(uint4*)(smem + A1H + row * 80 + ch * 16) = h;
    }
    // B1 fill: t^T [128][80B], 4 chunks of 16B per row
    #pragma unroll
    for (int it = 0; it < 2; it++) {
        int idx = it * 256 + tid;
        int row = idx >> 2, ch = idx & 3;
        uint32_t gb = (uint32_t)(l * DP + row) * 16u + ch * 4;
        *(uint4*)(smem + B1H + row * 80 + ch * 16) = *(const uint4*)(g_tp + gb);
    }
    // B2 fill: w_rbf^T [128][112B]
    #pragma unroll
    for (int it = 0; it < 3; it++) {
        int idx = it * 256 + tid;
        int row = idx / 6, ch = idx - row * 6;
        *(uint4*)(smem + B2H + row * 112 + ch * 16) = *(const uint4*)(g_wr + row * 24 + ch * 4);
    }
    __syncthreads();

    // A2 fill: rbf features fp16 [64][112B]
    {
        int m = tid >> 2, kg = tid & 3;
        float dist = dist_s[m];
        const float DMU = 20.0f / 35.0f, INV_SIG = 36.0f / 20.0f;
        #pragma unroll
        for (int kk = 0; kk < 6; kk++) {
            int k = kg * 12 + 2 * kk;
            float e0 = 0.f, e1 = 0.f;
            if (k < KRBF) {
                float u = (dist - (2.0f + (float)k * DMU)) * INV_SIG;
                e0 = __expf(-u * u);
            }
            if (k + 1 < KRBF) {
                float u = (dist - (2.0f + (float)(k + 1) * DMU)) * INV_SIG;
                e1 = __expf(-u * u);
            }
            *(uint32_t*)(smem + A2H + m * 112 + k * 2) = pk2(e0, e1);
        }
    }
    __syncthreads();

    // ---- ldmatrix address components ----
    uint32_t rr = lane & 7, q = lane >> 3;
    uint32_t a_r = (q & 1) << 3, a_k = (q >> 1) << 3;
    uint32_t b_r = (q >> 1) << 3, b_k = (q & 1) << 3;
    int M0 = (wid & 1) * 32, P0 = (wid >> 1) * 32;
    int r0 = lane >> 2, c2 = (lane & 3) * 2;

    // ---- pass 1: logits (K=32, 2 ks) ----
    uint32_t Ah[2][2][4];
    #pragma unroll
    for (int mt = 0; mt < 2; mt++)
        #pragma unroll
        for (int ks = 0; ks < 2; ks++)
            ldmx4(Ah[mt][ks], sb + A1H + (M0 + mt * 16 + rr + a_r) * 80 + (ks * 16 + a_k) * 2);

    float accL[2][4][4];
    #pragma unroll
    for (int mt = 0; mt < 2; mt++)
        #pragma unroll
        for (int nt = 0; nt < 4; nt++)
            #pragma unroll
            for (int j = 0; j < 4; j++) accL[mt][nt][j] = 0.f;

    #pragma unroll
    for (int npp = 0; npp < 2; npp++) {
        int n0 = P0 + npp * 16;
        uint32_t bbase = sb + B1H + (n0 + rr + b_r) * 80 + b_k * 2;
        #pragma unroll
        for (int ks = 0; ks < 2; ks++) {
            uint32_t bh[4];
            ldmx4(bh, bbase + ks * 32);
            #pragma unroll
            for (int mt = 0; mt < 2; mt++) {
                mma16816(accL[mt][2 * npp],     Ah[mt][ks], bh);
                mma16816(accL[mt][2 * npp + 1], Ah[mt][ks], bh + 2);
            }
        }
    }

    // ---- early sigmoid: gate packed half2 [mt][nt][2] ----
    uint32_t gate[2][4][2];
    #pragma unroll
    for (int nt = 0; nt < 4; nt++) {
        int pg = P0 + nt * 8 + c2;
        float2 bg = *(const float2*)(b_gate + pg);
        #pragma unroll
        for (int mt = 0; mt < 2; mt++) {
            gate[mt][nt][0] = pk2(sigmoid_t(accL[mt][nt][0] + bg.x),
                                  sigmoid_t(accL[mt][nt][1] + bg.y));
            gate[mt][nt][1] = pk2(sigmoid_t(accL[mt][nt][2] + bg.x),
                                  sigmoid_t(accL[mt][nt][3] + bg.y));
        }
    }

    // ---- pass 2: feat (K=48, 3 ks) + fused epilogue, direct stores ----
    uint32_t Fh[2][3][4];
    #pragma unroll
    for (int mt = 0; mt < 2; mt++)
        #pragma unroll
        for (int ks = 0; ks < 3; ks++)
            ldmx4(Fh[mt][ks], sb + A2H + (M0 + mt * 16 + rr + a_r) * 112 + (ks * 16 + a_k) * 2);

    #pragma unroll
    for (int npp = 0; npp < 2; npp++) {
        int n0 = P0 + npp * 16;
        uint32_t bbase = sb + B2H + (n0 + rr + b_r) * 112 + b_k * 2;
        float accF[2][2][4];
        #pragma unroll
        for (int mt = 0; mt < 2; mt++)
            #pragma unroll
            for (int nt = 0; nt < 2; nt++)
                #pragma unroll
                for (int j = 0; j < 4; j++) accF[mt][nt][j] = 0.f;
        #pragma unroll
        for (int ks = 0; ks < 3; ks++) {
            uint32_t bh[4];
            ldmx4(bh, bbase + ks * 32);
            #pragma unroll
            for (int mt = 0; mt < 2; mt++) {
                mma16816(accF[mt][0], Fh[mt][ks], bh);
                mma16816(accF[mt][1], Fh[mt][ks], bh + 2);
            }
        }
        // epilogue: feat * gate -> direct float2 stores
        #pragma unroll
        for (int mt = 0; mt < 2; mt++) {
            #pragma unroll
            for (int ntl = 0; ntl < 2; ntl++) {
                int nt = 2 * npp + ntl;
                int pg = P0 + nt * 8 + c2;
                float2 br = *(const float2*)(b_rbf + pg);
                const float* Fc = accF[mt][ntl];
                float2 g0 = __half22float2(*(const __half2*)&gate[mt][nt][0]);
                float2 g1 = __half22float2(*(const __half2*)&gate[mt][nt][1]);
                int m0 = mb + M0 + mt * 16 + r0;
                float* o0 = out + ((size_t)l * LL + m0) * DP + pg;
                float2 v0, v1;
                v0.x = (Fc[0] + br.x) * g0.x;
                v0.y = (Fc[1] + br.y) * g0.y;
                v1.x = (Fc[2] + br.x) * g1.x;
                v1.y = (Fc[3] + br.y) * g1.y;
                *(float2*)o0 = v0;
                *(float2*)(o0 + 8 * DP) = v1;
            }
        }
    }
}

// ---------------------------------------------------------------------------
extern "C" void kernel_launch(void* const* d_in, const int* in_sizes, int n_in,
                              void* d_out, int out_size)
{
    const float* xyz     = (const float*)d_in[0];
    const float* state   = (const float*)d_in[1];
    const float* ln_w    = (const float*)d_in[2];
    const float* ln_b    = (const float*)d_in[3];
    const float* w_rbf   = (const float*)d_in[4];
    const float* b_rbf   = (const float*)d_in[5];
    const float* w_left  = (const float*)d_in[6];
    const float* b_left  = (const float*)d_in[7];
    const float* w_right = (const float*)d_in[8];
    const float* b_right = (const float*)d_in[9];
    const float* w_gate  = (const float*)d_in[10];
    const float* b_gate  = (const float*)d_in[11];
    float* out = (float*)d_out;

    k_prep<<<LL, 256>>>(xyz, state, ln_w, ln_b, w_left, b_left, w_right, b_right, w_rbf);
    k_t<<<dim3(64, 8), 128>>>(w_gate);

    cudaFuncSetAttribute(k_main, cudaFuncAttributeMaxDynamicSharedMemorySize, SMTOT);
    k_main<<<dim3(LL, 8), 256, SMTOT>>>(b_rbf, b_gate, out);
}

// round 15
// speedup vs baseline: 1.5724x; 1.0332x over previous
#include <cuda_runtime.h>
#include <cuda_fp16.h>
#include <math.h>
#include <stdint.h>

#define LL 512
#define DS 256
#define HH 32
#define DP 128
#define KRBF 36

// ---------------- scratch globals ----------------
__device__ float    g_left[LL * HH];
__device__ float    g_right[LL * HH];      // [m][32] fp32
__device__ float    g_cas[LL * 4];
__device__ uint32_t g_tp[LL * DP * 16];    // t^T fp16: [l][p][16 words = 32 k]
__device__ uint32_t g_wr[DP * 24];         // w_rbf^T fp16: [p][24 words = 48 k]

// ---------------- helpers ----------------
__device__ __forceinline__ uint32_t smem_u32(const void* p) {
    uint32_t a;
    asm("{ .reg .u64 t; cvta.to.shared.u64 t, %1; cvt.u32.u64 %0, t; }" : "=r"(a) : "l"(p));
    return a;
}
__device__ __forceinline__ uint32_t pk2(float a, float b) {
    __half2 h = __floats2half2_rn(a, b);
    return *(uint32_t*)&h;
}
__device__ __forceinline__ void mma16816(float d[4], const uint32_t a[4], const uint32_t b[2]) {
    asm volatile("mma.sync.aligned.m16n8k16.row.col.f32.f16.f16.f32 "
        "{%0,%1,%2,%3}, {%4,%5,%6,%7}, {%8,%9}, {%0,%1,%2,%3};"
        : "+f"(d[0]), "+f"(d[1]), "+f"(d[2]), "+f"(d[3])
        : "r"(a[0]), "r"(a[1]), "r"(a[2]), "r"(a[3]), "r"(b[0]), "r"(b[1]));
}
__device__ __forceinline__ void ldmx4(uint32_t r[4], uint32_t addr) {
    asm volatile("ldmatrix.sync.aligned.m8n8.x4.shared.b16 {%0,%1,%2,%3}, [%4];"
        : "=r"(r[0]), "=r"(r[1]), "=r"(r[2]), "=r"(r[3]) : "r"(addr));
}
__device__ __forceinline__ float sigmoid_t(float x) {
    float t;
    asm("tanh.approx.f32 %0, %1;" : "=f"(t) : "f"(0.5f * x));
    return fmaf(0.5f, t, 0.5f);
}

// ---------------------------------------------------------------------------
// k_prep: LayerNorm + left/right projections + cas; block 0 packs w_rbf^T
// ---------------------------------------------------------------------------
__global__ __launch_bounds__(256) void k_prep(
    const float* __restrict__ xyz, const float* __restrict__ state,
    const float* __restrict__ ln_w, const float* __restrict__ ln_b,
    const float* __restrict__ w_left, const float* __restrict__ b_left,
    const float* __restrict__ w_right, const float* __restrict__ b_right,
    const float* __restrict__ w_rbf)
{
    int l = blockIdx.x, tid = threadIdx.x;
    __shared__ float st_s[DS];
    __shared__ float red[18];
    __shared__ float part[64][4];

    float x = state[l * DS + tid];
    float s = x, q = x * x;
    #pragma unroll
    for (int o = 16; o; o >>= 1) {
        s += __shfl_xor_sync(0xFFFFFFFFu, s, o);
        q += __shfl_xor_sync(0xFFFFFFFFu, q, o);
    }
    int wid = tid >> 5, lane = tid & 31;
    if (lane == 0) { red[wid] = s; red[8 + wid] = q; }
    __syncthreads();
    if (tid == 0) {
        float S = 0.f, Q = 0.f;
        #pragma unroll
        for (int i = 0; i < 8; i++) { S += red[i]; Q += red[8 + i]; }
        float mu = S * (1.0f / DS);
        float var = Q * (1.0f / DS) - mu * mu;
        red[16] = mu; red[17] = rsqrtf(var + 1e-5f);
    }
    __syncthreads();
    st_s[tid] = (x - red[16]) * red[17] * ln_w[tid] + ln_b[tid];
    __syncthreads();

    {
        int j = tid & 31, half = (tid >> 5) & 1, seg = tid >> 6;
        const float* w = half ? w_right : w_left;
        float acc0 = 0.f, acc1 = 0.f;
        int i0 = seg * 64;
        #pragma unroll 16
        for (int i = 0; i < 64; i += 2) {
            acc0 += st_s[i0 + i]     * w[(i0 + i) * HH + j];
            acc1 += st_s[i0 + i + 1] * w[(i0 + i + 1) * HH + j];
        }
        part[half * 32 + j][seg] = acc0 + acc1;
    }
    __syncthreads();
    if (tid < 64) {
        int j = tid & 31, half = tid >> 5;
        float a = part[tid][0] + part[tid][1] + part[tid][2] + part[tid][3]
                + (half ? b_right[j] : b_left[j]);
        if (half) g_right[l * HH + j] = a;
        else      g_left[l * HH + j] = a;
    }
    if (tid < 3) g_cas[l * 4 + tid] = xyz[l * 9 + 3 + tid];

    if (blockIdx.x == 0 && tid < DP) {
        #pragma unroll
        for (int c = 0; c < 24; c++) {
            int k0 = 2 * c, k1 = 2 * c + 1;
            float v0 = (k0 < KRBF) ? w_rbf[k0 * DP + tid] : 0.f;
            float v1 = (k1 < KRBF) ? w_rbf[k1 * DP + tid] : 0.f;
            g_wr[tid * 24 + c] = pk2(v0, v1);
        }
    }
}

// ---------------------------------------------------------------------------
// k_t: t[l,k,p] = sum_i left[l,i]*Wg[i,k,p]; emit t^T fp16 [l][p][k], stride 16
// grid = (32 lb, 8 jb): 16 l x 4 j x 128 p per block, 128 threads
// ---------------------------------------------------------------------------
__global__ __launch_bounds__(128) void k_t(const float* __restrict__ w_gate)
{
    __shared__ float ls[16 * HH];
    int lb = blockIdx.x * 16, j0 = blockIdx.y * 4, p = threadIdx.x;
    #pragma unroll
    for (int i = p; i < 16 * HH; i += 128) ls[i] = g_left[lb * HH + i];
    __syncthreads();

    float acc[16][4];
    #pragma unroll
    for (int lt = 0; lt < 16; lt++)
        #pragma unroll
        for (int qj = 0; qj < 4; qj++) acc[lt][qj] = 0.f;

    #pragma unroll 4
    for (int i = 0; i < HH; i++) {
        float wv[4];
        #pragma unroll
        for (int qj = 0; qj < 4; qj++)
            wv[qj] = w_gate[(i * HH + j0 + qj) * DP + p];
        #pragma unroll
        for (int lt = 0; lt < 16; lt++) {
            float lv = ls[lt * HH + i];
            #pragma unroll
            for (int qj = 0; qj < 4; qj++) acc[lt][qj] += lv * wv[qj];
        }
    }
    int c0 = j0 >> 1;   // word index, 2 words per block
    #pragma unroll
    for (int lt = 0; lt < 16; lt++) {
        uint32_t h0 = pk2(acc[lt][0], acc[lt][1]);
        uint32_t h1 = pk2(acc[lt][2], acc[lt][3]);
        uint32_t base = (uint32_t)((lb + lt) * DP + p) * 16u + c0;
        *(uint2*)(g_tp + base) = make_uint2(h0, h1);
    }
}

// ---------------------------------------------------------------------------
// k_main: mma.sync fp16 single-product, natural regs.
// Block = (l, 64 m) x 128 p, 8 warps; warp tile 32m x 32p.
// A2 fill: one STS.128 per (m, 8-k group) task, dist inline; single sync.
// ---------------------------------------------------------------------------
#define A1H 0
#define A2H 5120
#define B1H 12288
#define B2H 22528
#define SMTOT 36864

__global__ __launch_bounds__(256) void k_main(
    const float* __restrict__ b_rbf, const float* __restrict__ b_gate,
    float* __restrict__ out)
{
    extern __shared__ char smem[];
    uint32_t sb = smem_u32(smem);
    int tid = threadIdx.x, lane = tid & 31, wid = tid >> 5;
    int l = blockIdx.x, mb = blockIdx.y * 64;

    // A1 fill: right -> fp16 [64][80B]
    {
        int row = tid >> 2, ch = tid & 3;
        const float4* src = (const float4*)(g_right + (mb + row) * HH + ch * 8);
        float4 x = src[0], y = src[1];
        uint4 h = make_uint4(pk2(x.x, x.y), pk2(x.z, x.w), pk2(y.x, y.y), pk2(y.z, y.w));
        *(uint4*)(smem + A1H + row * 80 + ch * 16) = h;
    }
    // B1 fill: t^T [128][80B], 4 chunks of 16B per row
    #pragma unroll
    for (int it = 0; it < 2; it++) {
        int idx = it * 256 + tid;
        int row = idx >> 2, ch = idx & 3;
        uint32_t gb = (uint32_t)(l * DP + row) * 16u + ch * 4;
        *(uint4*)(smem + B1H + row * 80 + ch * 16) = *(const uint4*)(g_tp + gb);
    }
    // B2 fill: w_rbf^T [128][112B]
    #pragma unroll
    for (int it = 0; it < 3; it++) {
        int idx = it * 256 + tid;
        int row = idx / 6, ch = idx - row * 6;
        *(uint4*)(smem + B2H + row * 112 + ch * 16) = *(const uint4*)(g_wr + row * 24 + ch * 4);
    }
    // A2 fill: rbf features fp16 [64][112B], (m, 8-k group) -> STS.128, dist inline
    {
        float clx = g_cas[l * 4], cly = g_cas[l * 4 + 1], clz = g_cas[l * 4 + 2];
        const float DMU = 20.0f / 35.0f, INV_SIG = 36.0f / 20.0f;
        #pragma unroll
        for (int it = 0; it < 2; it++) {
            int idx = it * 256 + tid;
            if (idx < 384) {
                int m = idx / 6, kg = idx - m * 6;
                int gm = mb + m;
                float dx = g_cas[gm * 4]     - clx;
                float dy = g_cas[gm * 4 + 1] - cly;
                float dz = g_cas[gm * 4 + 2] - clz;
                float dist = sqrtf(fmaxf(dx * dx + dy * dy + dz * dz, 1e-12f));
                int k0 = kg * 8;
                uint32_t wbuf[4];
                #pragma unroll
                for (int pr = 0; pr < 4; pr++) {
                    int k = k0 + 2 * pr;
                    float e0 = 0.f, e1 = 0.f;
                    if (k < KRBF) {
                        float u = (dist - (2.0f + (float)k * DMU)) * INV_SIG;
                        e0 = __expf(-u * u);
                    }
                    if (k + 1 < KRBF) {
                        float u = (dist - (2.0f + (float)(k + 1) * DMU)) * INV_SIG;
                        e1 = __expf(-u * u);
                    }
                    wbuf[pr] = pk2(e0, e1);
                }
                *(uint4*)(smem + A2H + m * 112 + k0 * 2) =
                    make_uint4(wbuf[0], wbuf[1], wbuf[2], wbuf[3]);
            }
        }
    }
    __syncthreads();

    // ---- ldmatrix address components ----
    uint32_t rr = lane & 7, q = lane >> 3;
    uint32_t a_r = (q & 1) << 3, a_k = (q >> 1) << 3;
    uint32_t b_r = (q >> 1) << 3, b_k = (q & 1) << 3;
    int M0 = (wid & 1) * 32, P0 = (wid >> 1) * 32;
    int r0 = lane >> 2, c2 = (lane & 3) * 2;

    // ---- pass 1: logits (K=32, 2 ks) ----
    uint32_t Ah[2][2][4];
    #pragma unroll
    for (int mt = 0; mt < 2; mt++)
        #pragma unroll
        for (int ks = 0; ks < 2; ks++)
            ldmx4(Ah[mt][ks], sb + A1H + (M0 + mt * 16 + rr + a_r) * 80 + (ks * 16 + a_k) * 2);

    float accL[2][4][4];
    #pragma unroll
    for (int mt = 0; mt < 2; mt++)
        #pragma unroll
        for (int nt = 0; nt < 4; nt++)
            #pragma unroll
            for (int j = 0; j < 4; j++) accL[mt][nt][j] = 0.f;

    #pragma unroll
    for (int npp = 0; npp < 2; npp++) {
        int n0 = P0 + npp * 16;
        uint32_t bbase = sb + B1H + (n0 + rr + b_r) * 80 + b_k * 2;
        #pragma unroll
        for (int ks = 0; ks < 2; ks++) {
            uint32_t bh[4];
            ldmx4(bh, bbase + ks * 32);
            #pragma unroll
            for (int mt = 0; mt < 2; mt++) {
                mma16816(accL[mt][2 * npp],     Ah[mt][ks], bh);
                mma16816(accL[mt][2 * npp + 1], Ah[mt][ks], bh + 2);
            }
        }
    }

    // ---- early sigmoid: gate packed half2 [mt][nt][2] ----
    uint32_t gate[2][4][2];
    #pragma unroll
    for (int nt = 0; nt < 4; nt++) {
        int pg = P0 + nt * 8 + c2;
        float2 bg = *(const float2*)(b_gate + pg);
        #pragma unroll
        for (int mt = 0; mt < 2; mt++) {
            gate[mt][nt][0] = pk2(sigmoid_t(accL[mt][nt][0] + bg.x),
                                  sigmoid_t(accL[mt][nt][1] + bg.y));
            gate[mt][nt][1] = pk2(sigmoid_t(accL[mt][nt][2] + bg.x),
                                  sigmoid_t(accL[mt][nt][3] + bg.y));
        }
    }

    // ---- pass 2: feat (K=48, 3 ks) + fused epilogue, direct stores ----
    uint32_t Fh[2][3][4];
    #pragma unroll
    for (int mt = 0; mt < 2; mt++)
        #pragma unroll
        for (int ks = 0; ks < 3; ks++)
            ldmx4(Fh[mt][ks], sb + A2H + (M0 + mt * 16 + rr + a_r) * 112 + (ks * 16 + a_k) * 2);

    #pragma unroll
    for (int npp = 0; npp < 2; npp++) {
        int n0 = P0 + npp * 16;
        uint32_t bbase = sb + B2H + (n0 + rr + b_r) * 112 + b_k * 2;
        float accF[2][2][4];
        #pragma unroll
        for (int mt = 0; mt < 2; mt++)
            #pragma unroll
            for (int nt = 0; nt < 2; nt++)
                #pragma unroll
                for (int j = 0; j < 4; j++) accF[mt][nt][j] = 0.f;
        #pragma unroll
        for (int ks = 0; ks < 3; ks++) {
            uint32_t bh[4];
            ldmx4(bh, bbase + ks * 32);
            #pragma unroll
            for (int mt = 0; mt < 2; mt++) {
                mma16816(accF[mt][0], Fh[mt][ks], bh);
                mma16816(accF[mt][1], Fh[mt][ks], bh + 2);
            }
        }
        // epilogue: feat * gate -> direct float2 stores
        #pragma unroll
        for (int mt = 0; mt < 2; mt++) {
            #pragma unroll
            for (int ntl = 0; ntl < 2; ntl++) {
                int nt = 2 * npp + ntl;
                int pg = P0 + nt * 8 + c2;
                float2 br = *(const float2*)(b_rbf + pg);
                const float* Fc = accF[mt][ntl];
                float2 g0 = __half22float2(*(const __half2*)&gate[mt][nt][0]);
                float2 g1 = __half22float2(*(const __half2*)&gate[mt][nt][1]);
                int m0 = mb + M0 + mt * 16 + r0;
                float* o0 = out + ((size_t)l * LL + m0) * DP + pg;
                float2 v0, v1;
                v0.x = (Fc[0] + br.x) * g0.x;
                v0.y = (Fc[1] + br.y) * g0.y;
                v1.x = (Fc[2] + br.x) * g1.x;
                v1.y = (Fc[3] + br.y) * g1.y;
                *(float2*)o0 = v0;
                *(float2*)(o0 + 8 * DP) = v1;
            }
        }
    }
}

// ---------------------------------------------------------------------------
extern "C" void kernel_launch(void* const* d_in, const int* in_sizes, int n_in,
                              void* d_out, int out_size)
{
    const float* xyz     = (const float*)d_in[0];
    const float* state   = (const float*)d_in[1];
    const float* ln_w    = (const float*)d_in[2];
    const float* ln_b    = (const float*)d_in[3];
    const float* w_rbf   = (const float*)d_in[4];
    const float* b_rbf   = (const float*)d_in[5];
    const float* w_left  = (const float*)d_in[6];
    const float* b_left  = (const float*)d_in[7];
    const float* w_right = (const float*)d_in[8];
    const float* b_right = (const float*)d_in[9];
    const float* w_gate  = (const float*)d_in[10];
    const float* b_gate  = (const float*)d_in[11];
    float* out = (float*)d_out;

    k_prep<<<LL, 256>>>(xyz, state, ln_w, ln_b, w_left, b_left, w_right, b_right, w_rbf);
    k_t<<<dim3(32, 8), 128>>>(w_gate);

    cudaFuncSetAttribute(k_main, cudaFuncAttributeMaxDynamicSharedMemorySize, SMTOT);
    k_main<<<dim3(LL, 8), 256, SMTOT>>>(b_rbf, b_gate, out);
}